// round 2
// baseline (speedup 1.0000x reference)
#include <cuda_runtime.h>
#include <math.h>
#include <stdint.h>

#define RTOT 2048           // 8 * 256 rows
#define VOC  32000
#define DIM  100
#define EPSC 1e-20f

#define TM     64           // rows per gemm tile
#define KSPLIT 32
#define KCHUNK (VOC / KSPLIT)   // 1000
#define KB     40               // k-depth staged per iteration (1000 % 40 == 0)
#define WPAD   68               // padded row stride for w_s

// ---------------- scratch (__device__ globals; no allocation) ----------------
__device__ float d_mz[RTOT];
__device__ float d_sz[RTOT];
__device__ float d_ent[RTOT];
__device__ int   d_fillsrc[RTOT];   // -1 => gemm row, else gather source index
__device__ int   d_rows[RTOT];      // compacted gemm row list
__device__ int   d_count;
__device__ int   d_is64;
__device__ float d_part[(size_t)KSPLIT * RTOT * DIM];   // 26.2 MB split-K partials

// ---------------- f32x2 helpers (sm_103a packed fp32) ----------------
__device__ __forceinline__ unsigned long long pk2(float lo, float hi) {
    unsigned long long r;
    asm("mov.b64 %0, {%1, %2};" : "=l"(r) : "f"(lo), "f"(hi));
    return r;
}
__device__ __forceinline__ float2 unpk2(unsigned long long v) {
    float2 r;
    asm("mov.b64 {%0, %1}, %2;" : "=f"(r.x), "=f"(r.y) : "l"(v));
    return r;
}
__device__ __forceinline__ void fma2(unsigned long long& d, unsigned long long a, unsigned long long b) {
    asm("fma.rn.f32x2 %0, %1, %2, %0;" : "+l"(d) : "l"(a), "l"(b));
}

// Gumbel: inner log MUST be precise (u near 1 -> -log(u) tiny; __logf's
// absolute error becomes catastrophic relative error there, flipping argmax
// and corrupting the dominant softmax weight). Outer log can be fast.
__device__ __forceinline__ float gumbel_of(float u) {
    float t = -logf(u + EPSC);          // precise
    return -__logf(t + EPSC);           // fast: abs error in g ~5e-7, harmless
}

// ---------------- init: zero counter + dtype sniff for inp_word ----------------
__global__ void init_kernel(const void* inp) {
    d_count = 0;
    const long long* p = (const long long*)inp;
    bool is64 = true;
#pragma unroll
    for (int i = 0; i < 8; i++) {
        long long v = p[i];
        if (v < 0 || v >= VOC) is64 = false;   // int32 data read as i64 -> huge values
    }
    d_is64 = is64 ? 1 : 0;
}

// ---------------- stats: one streaming pass per row ----------------
__global__ __launch_bounds__(256) void stats_kernel(
    const float* __restrict__ logits,
    const float* __restrict__ gum,
    const void*  __restrict__ inp,
    const int*   __restrict__ msk,
    float* __restrict__ out_word)
{
    const int row = blockIdx.x;
    const float4* lrow = (const float4*)(logits + (size_t)row * VOC);
    const float4* grow = (const float4*)(gum    + (size_t)row * VOC);

    float ml = -INFINITY, sl = 0.f, tl = 0.f;   // logits softmax stats
    float mz = -INFINITY, sz = 0.f;             // z = logits + gumbel
    int   ai = 0;

    for (int v4 = threadIdx.x; v4 < VOC / 4; v4 += 256) {
        float4 L = lrow[v4];
        float4 U = grow[v4];
        float ls[4] = {L.x, L.y, L.z, L.w};
        float us[4] = {U.x, U.y, U.z, U.w};
#pragma unroll
        for (int j = 0; j < 4; j++) {
            float l = ls[j];
            float z = l + gumbel_of(us[j]);
            if (l > ml) { float c = __expf(ml - l); sl = sl * c + 1.f; tl = tl * c + l; ml = l; }
            else        { float e = __expf(l - ml); sl += e; tl += l * e; }
            if (z > mz) { sz = sz * __expf(mz - z) + 1.f; mz = z; ai = 4 * v4 + j; }
            else        { sz += __expf(z - mz); }
        }
    }

    // warp reduce
    const unsigned FULL = 0xffffffffu;
#pragma unroll
    for (int off = 16; off; off >>= 1) {
        float ml2 = __shfl_down_sync(FULL, ml, off);
        float sl2 = __shfl_down_sync(FULL, sl, off);
        float tl2 = __shfl_down_sync(FULL, tl, off);
        float mz2 = __shfl_down_sync(FULL, mz, off);
        float sz2 = __shfl_down_sync(FULL, sz, off);
        int   ai2 = __shfl_down_sync(FULL, ai, off);
        if (ml2 > ml) { float c = __expf(ml - ml2); sl = sl * c + sl2; tl = tl * c + tl2; ml = ml2; }
        else if (sl2 > 0.f) { float c = __expf(ml2 - ml); sl += sl2 * c; tl += tl2 * c; }
        if (mz2 > mz || (mz2 == mz && ai2 < ai)) {
            float c = __expf(mz - mz2); sz = sz * c + sz2; mz = mz2; ai = ai2;
        } else if (sz2 > 0.f) { sz += sz2 * __expf(mz2 - mz); }
    }

    __shared__ float s_ml[8], s_sl[8], s_tl[8], s_mz[8], s_sz[8];
    __shared__ int   s_ai[8];
    int wid = threadIdx.x >> 5, lid = threadIdx.x & 31;
    if (lid == 0) { s_ml[wid]=ml; s_sl[wid]=sl; s_tl[wid]=tl; s_mz[wid]=mz; s_sz[wid]=sz; s_ai[wid]=ai; }
    __syncthreads();

    if (wid == 0) {
        bool live = (lid < 8);
        ml = live ? s_ml[lid] : -INFINITY;
        sl = live ? s_sl[lid] : 0.f;
        tl = live ? s_tl[lid] : 0.f;
        mz = live ? s_mz[lid] : -INFINITY;
        sz = live ? s_sz[lid] : 0.f;
        ai = live ? s_ai[lid] : 0x7fffffff;
#pragma unroll
        for (int off = 4; off; off >>= 1) {
            float ml2 = __shfl_down_sync(FULL, ml, off);
            float sl2 = __shfl_down_sync(FULL, sl, off);
            float tl2 = __shfl_down_sync(FULL, tl, off);
            float mz2 = __shfl_down_sync(FULL, mz, off);
            float sz2 = __shfl_down_sync(FULL, sz, off);
            int   ai2 = __shfl_down_sync(FULL, ai, off);
            if (ml2 > ml) { float c = __expf(ml - ml2); sl = sl * c + sl2; tl = tl * c + tl2; ml = ml2; }
            else if (sl2 > 0.f) { float c = __expf(ml2 - ml); sl += sl2 * c; tl += tl2 * c; }
            if (mz2 > mz || (mz2 == mz && ai2 < ai)) {
                float c = __expf(mz - mz2); sz = sz * c + sz2; mz = mz2; ai = ai2;
            } else if (sz2 > 0.f) { sz += sz2 * __expf(mz2 - mz); }
        }
        if (lid == 0) {
            float lse = ml + __logf(sl);
            float ent = tl / sl - lse;
            long long iw = d_is64 ? ((const long long*)inp)[row]
                                  : (long long)((const int*)inp)[row];
            int m = msk[row];
            bool safe = (ai != (int)iw);
            long long obf = m ? (safe ? (long long)ai : 0LL) : iw;
            out_word[row] = (float)obf;
            d_ent[row]    = m ? ent : 0.f;
            d_mz[row] = mz;
            d_sz[row] = sz;
            if (m && safe) {
                int p = atomicAdd(&d_count, 1);
                d_rows[p] = row;
                d_fillsrc[row] = -1;
            } else {
                d_fillsrc[row] = m ? 0 : (int)iw;
            }
        }
    }
}

// ---------------- fill: embedding gather for non-gemm rows ----------------
__global__ __launch_bounds__(128) void fill_kernel(const float* __restrict__ W,
                                                   float* __restrict__ out_emb)
{
    int row = blockIdx.x;
    int src = d_fillsrc[row];
    if (src < 0) return;
    int d = threadIdx.x;
    if (d < DIM)
        out_emb[(size_t)row * DIM + d] = W[(size_t)src * DIM + d];
}

// ---------------- gemm: split-K, smem-staged, packed f32x2 FMA ----------------
__global__ __launch_bounds__(400) void gemm_kernel(
    const float* __restrict__ logits,
    const float* __restrict__ gum,
    const float* __restrict__ W)
{
    __shared__ float w_s[KB][WPAD];      // [k][row-in-tile]
    __shared__ float W_s[KB][DIM];       // [k][col]

    const int nrows = d_count;
    const int r0 = blockIdx.x * TM;
    if (r0 >= nrows) return;
    const int ks = blockIdx.y;
    const int tx = threadIdx.x;                 // 0..24 (4 cols each)
    const int ty = threadIdx.y;                 // 0..15 (4 rows each)
    const int tid = ty * 25 + tx;               // 0..399
    const int kbase = ks * KCHUNK;

    unsigned long long acc[8];                  // 4 rows x 2 col-pairs
#pragma unroll
    for (int i = 0; i < 8; i++) acc[i] = 0ull;

    for (int kb = 0; kb < KCHUNK; kb += KB) {
        // stage w: recompute exp(z - m_z) for this tile's rows, k-slab
        for (int e = tid; e < KB * TM; e += 400) {
            int kl = e % KB;
            int r  = e / KB;
            int pos = r0 + r;
            float w = 0.f;
            if (pos < nrows) {
                int row = d_rows[pos];
                size_t idx = (size_t)row * VOC + (kbase + kb + kl);
                float l = logits[idx];
                float u = gum[idx];
                w = __expf(l + gumbel_of(u) - d_mz[row]);
            }
            w_s[kl][r] = w;
        }
        // stage W slab
        for (int e = tid; e < KB * DIM; e += 400) {
            int kl = e / DIM;
            int c  = e % DIM;
            W_s[kl][c] = W[(size_t)(kbase + kb + kl) * DIM + c];
        }
        __syncthreads();

#pragma unroll 8
        for (int k = 0; k < KB; k++) {
            float4 wv = *reinterpret_cast<const float4*>(&w_s[k][ty << 2]);
            float4 Wv = *reinterpret_cast<const float4*>(&W_s[k][tx << 2]);
            unsigned long long b0 = pk2(Wv.x, Wv.y);
            unsigned long long b1 = pk2(Wv.z, Wv.w);
            unsigned long long a0 = pk2(wv.x, wv.x);
            unsigned long long a1 = pk2(wv.y, wv.y);
            unsigned long long a2 = pk2(wv.z, wv.z);
            unsigned long long a3 = pk2(wv.w, wv.w);
            fma2(acc[0], a0, b0); fma2(acc[1], a0, b1);
            fma2(acc[2], a1, b0); fma2(acc[3], a1, b1);
            fma2(acc[4], a2, b0); fma2(acc[5], a2, b1);
            fma2(acc[6], a3, b0); fma2(acc[7], a3, b1);
        }
        __syncthreads();
    }

#pragma unroll
    for (int r = 0; r < 4; r++) {
        int pos = r0 + (ty << 2) + r;
        float2 lo = unpk2(acc[r * 2]);
        float2 hi = unpk2(acc[r * 2 + 1]);
        float4 v = make_float4(lo.x, lo.y, hi.x, hi.y);
        *reinterpret_cast<float4*>(&d_part[((size_t)ks * RTOT + pos) * DIM + (tx << 2)]) = v;
    }
}

// ---------------- reduce split-K partials, normalize by s_z ----------------
__global__ __launch_bounds__(128) void reduce_kernel(float* __restrict__ out_emb)
{
    int pos = blockIdx.x;
    if (pos >= d_count) return;
    int d = threadIdx.x;
    if (d >= DIM) return;
    float s = 0.f;
#pragma unroll
    for (int k = 0; k < KSPLIT; k++)
        s += d_part[((size_t)k * RTOT + pos) * DIM + d];
    int row = d_rows[pos];
    out_emb[(size_t)row * DIM + d] = s / d_sz[row];
}

// ---------------- entropy loss ----------------
__global__ __launch_bounds__(256) void ent_kernel(const int* __restrict__ msk,
                                                  float* __restrict__ ent_out)
{
    __shared__ float ssum[256];
    __shared__ int   scnt[256];
    float s = 0.f; int c = 0;
    for (int i = threadIdx.x; i < RTOT; i += 256) { s += d_ent[i]; c += msk[i]; }
    ssum[threadIdx.x] = s; scnt[threadIdx.x] = c;
    __syncthreads();
    for (int off = 128; off; off >>= 1) {
        if (threadIdx.x < off) {
            ssum[threadIdx.x] += ssum[threadIdx.x + off];
            scnt[threadIdx.x] += scnt[threadIdx.x + off];
        }
        __syncthreads();
    }
    if (threadIdx.x == 0)
        ent_out[0] = ssum[0] / ((float)scnt[0] * (float)VOC);
}

// ---------------- launch ----------------
extern "C" void kernel_launch(void* const* d_in, const int* in_sizes, int n_in,
                              void* d_out, int out_size)
{
    const float* logits = (const float*)d_in[0];
    const float* gum    = (const float*)d_in[1];
    const void*  inp    = d_in[2];
    const int*   msk    = (const int*)d_in[3];
    const float* W      = (const float*)d_in[4];

    float* out      = (float*)d_out;
    float* out_word = out;                       // [2048]
    float* out_emb  = out + RTOT;                // [2048*100]
    float* out_ent  = out + RTOT + RTOT * DIM;   // [1]

    init_kernel<<<1, 1>>>(inp);
    stats_kernel<<<RTOT, 256>>>(logits, gum, inp, msk, out_word);
    fill_kernel<<<RTOT, 128>>>(W, out_emb);
    dim3 gg(RTOT / TM, KSPLIT), gb(25, 16);
    gemm_kernel<<<gg, gb>>>(logits, gum, W);
    reduce_kernel<<<RTOT, 128>>>(out_emb);
    ent_kernel<<<1, 256>>>(msk, out_ent);
}

// round 3
// speedup vs baseline: 1.2623x; 1.2623x over previous
#include <cuda_runtime.h>
#include <math.h>
#include <stdint.h>

#define RTOT 2048           // 8 * 256 rows
#define VOC  32000
#define DIM  100
#define EPSC 1e-20f

#define TM     32               // rows per gemm tile
#define KSPLIT 16
#define KCHUNK (VOC / KSPLIT)   // 2000
#define KB     20               // k-depth staged per iteration
#define NITER  (KCHUNK / KB)    // 100

// ---------------- scratch (__device__ globals; no allocation) ----------------
__device__ float d_mz[RTOT];
__device__ float d_sz[RTOT];
__device__ float d_ent[RTOT];
__device__ int   d_fillsrc[RTOT];   // -1 => gemm row, else gather source index
__device__ int   d_rows[RTOT];      // compacted gemm row list
__device__ int   d_count;
__device__ int   d_is64;
__device__ float d_part[(size_t)KSPLIT * RTOT * DIM];      // 13.1 MB split-K partials
__device__ float d_zbuf[(size_t)RTOT * VOC];               // 262 MB: z for masked rows

// ---------------- f32x2 helpers (sm_103a packed fp32) ----------------
__device__ __forceinline__ void fma2(unsigned long long& d, unsigned long long a, unsigned long long b) {
    asm("fma.rn.f32x2 %0, %1, %2, %0;" : "+l"(d) : "l"(a), "l"(b));
}
__device__ __forceinline__ float2 unpk2(unsigned long long v) {
    float2 r;
    asm("mov.b64 {%0, %1}, %2;" : "=f"(r.x), "=f"(r.y) : "l"(v));
    return r;
}

// Gumbel with argmax-safe inner log:
//  u <= 0.9 : t = -__logf(u)        (MUFU; rel err of t <= ~2e-6 there)
//  u >  0.9 : t = -log1p(-(1-u))    via 5-term Maclaurin (rel err ~2e-6)
// (plain __logf near u=1 has catastrophic relative error in t and flips argmax)
__device__ __forceinline__ float gumbel_of(float u) {
    float t;
    if (u > 0.9f) {
        float d = 1.0f - u;   // exact (Sterbenz)
        t = d * (1.0f + d * (0.5f + d * (0.33333334f + d * (0.25f + d * 0.2f))));
    } else {
        t = -__logf(u + EPSC);
    }
    return -__logf(t + EPSC);
}

// ---------------- init: zero counter + dtype sniff for inp_word ----------------
__global__ void init_kernel(const void* inp) {
    d_count = 0;
    const long long* p = (const long long*)inp;
    bool is64 = true;
#pragma unroll
    for (int i = 0; i < 8; i++) {
        long long v = p[i];
        if (v < 0 || v >= VOC) is64 = false;   // int32 data read as i64 -> huge values
    }
    d_is64 = is64 ? 1 : 0;
}

// ---------------- stats: one streaming pass per row; stores z for masked rows --
__global__ __launch_bounds__(256) void stats_kernel(
    const float* __restrict__ logits,
    const float* __restrict__ gum,
    const void*  __restrict__ inp,
    const int*   __restrict__ msk,
    float* __restrict__ out_word)
{
    const int row = blockIdx.x;
    const int m = msk[row];
    const float4* lrow = (const float4*)(logits + (size_t)row * VOC);
    const float4* grow = (const float4*)(gum    + (size_t)row * VOC);
    float4* zrow = (float4*)(d_zbuf + (size_t)row * VOC);

    float ml = -INFINITY, sl = 0.f, tl = 0.f;   // logits softmax stats
    float mz = -INFINITY, sz = 0.f;             // z = logits + gumbel
    int   ai = 0;

    for (int v4 = threadIdx.x; v4 < VOC / 4; v4 += 256) {
        float4 L = lrow[v4];
        float4 U = grow[v4];
        float ls[4] = {L.x, L.y, L.z, L.w};
        float us[4] = {U.x, U.y, U.z, U.w};
        float zs[4];
#pragma unroll
        for (int j = 0; j < 4; j++) {
            float l = ls[j];
            float z = l + gumbel_of(us[j]);
            zs[j] = z;
            if (l > ml) { float c = __expf(ml - l); sl = sl * c + 1.f; tl = tl * c + l; ml = l; }
            else        { float e = __expf(l - ml); sl += e; tl += l * e; }
            if (z > mz) { sz = sz * __expf(mz - z) + 1.f; mz = z; ai = 4 * v4 + j; }
            else        { sz += __expf(z - mz); }
        }
        if (m) zrow[v4] = make_float4(zs[0], zs[1], zs[2], zs[3]);
    }

    // warp reduce
    const unsigned FULL = 0xffffffffu;
#pragma unroll
    for (int off = 16; off; off >>= 1) {
        float ml2 = __shfl_down_sync(FULL, ml, off);
        float sl2 = __shfl_down_sync(FULL, sl, off);
        float tl2 = __shfl_down_sync(FULL, tl, off);
        float mz2 = __shfl_down_sync(FULL, mz, off);
        float sz2 = __shfl_down_sync(FULL, sz, off);
        int   ai2 = __shfl_down_sync(FULL, ai, off);
        if (ml2 > ml) { float c = __expf(ml - ml2); sl = sl * c + sl2; tl = tl * c + tl2; ml = ml2; }
        else if (sl2 > 0.f) { float c = __expf(ml2 - ml); sl += sl2 * c; tl += tl2 * c; }
        if (mz2 > mz || (mz2 == mz && ai2 < ai)) {
            float c = __expf(mz - mz2); sz = sz * c + sz2; mz = mz2; ai = ai2;
        } else if (sz2 > 0.f) { sz += sz2 * __expf(mz2 - mz); }
    }

    __shared__ float s_ml[8], s_sl[8], s_tl[8], s_mz[8], s_sz[8];
    __shared__ int   s_ai[8];
    int wid = threadIdx.x >> 5, lid = threadIdx.x & 31;
    if (lid == 0) { s_ml[wid]=ml; s_sl[wid]=sl; s_tl[wid]=tl; s_mz[wid]=mz; s_sz[wid]=sz; s_ai[wid]=ai; }
    __syncthreads();

    if (wid == 0) {
        bool live = (lid < 8);
        ml = live ? s_ml[lid] : -INFINITY;
        sl = live ? s_sl[lid] : 0.f;
        tl = live ? s_tl[lid] : 0.f;
        mz = live ? s_mz[lid] : -INFINITY;
        sz = live ? s_sz[lid] : 0.f;
        ai = live ? s_ai[lid] : 0x7fffffff;
#pragma unroll
        for (int off = 4; off; off >>= 1) {
            float ml2 = __shfl_down_sync(FULL, ml, off);
            float sl2 = __shfl_down_sync(FULL, sl, off);
            float tl2 = __shfl_down_sync(FULL, tl, off);
            float mz2 = __shfl_down_sync(FULL, mz, off);
            float sz2 = __shfl_down_sync(FULL, sz, off);
            int   ai2 = __shfl_down_sync(FULL, ai, off);
            if (ml2 > ml) { float c = __expf(ml - ml2); sl = sl * c + sl2; tl = tl * c + tl2; ml = ml2; }
            else if (sl2 > 0.f) { float c = __expf(ml2 - ml); sl += sl2 * c; tl += tl2 * c; }
            if (mz2 > mz || (mz2 == mz && ai2 < ai)) {
                float c = __expf(mz - mz2); sz = sz * c + sz2; mz = mz2; ai = ai2;
            } else if (sz2 > 0.f) { sz += sz2 * __expf(mz2 - mz); }
        }
        if (lid == 0) {
            float lse = ml + __logf(sl);
            float ent = tl / sl - lse;
            long long iw = d_is64 ? ((const long long*)inp)[row]
                                  : (long long)((const int*)inp)[row];
            bool safe = (ai != (int)iw);
            long long obf = m ? (safe ? (long long)ai : 0LL) : iw;
            out_word[row] = (float)obf;
            d_ent[row]    = m ? ent : 0.f;
            d_mz[row] = mz;
            d_sz[row] = sz;
            if (m && safe) {
                int p = atomicAdd(&d_count, 1);
                d_rows[p] = row;
                d_fillsrc[row] = -1;
            } else {
                d_fillsrc[row] = m ? 0 : (int)iw;
            }
        }
    }
}

// ---------------- fill: embedding gather for non-gemm rows ----------------
__global__ __launch_bounds__(128) void fill_kernel(const float* __restrict__ W,
                                                   float* __restrict__ out_emb)
{
    int row = blockIdx.x;
    int src = d_fillsrc[row];
    if (src < 0) return;
    int d = threadIdx.x;
    if (d < DIM)
        out_emb[(size_t)row * DIM + d] = W[(size_t)src * DIM + d];
}

// ---------------- gemm: split-K, reg-prefetch, pre-duplicated f32x2 weights ----
__global__ __launch_bounds__(200) void gemm_kernel(const float* __restrict__ W)
{
    __shared__ float2 w2_s[KB][TM + 2];   // duplicated (w,w); +2 pad kills STS conflicts
    __shared__ float  W_s[KB][DIM];       // [k][col]
    __shared__ float  mz_s[TM];
    __shared__ int    row_s[TM];

    const int nrows = d_count;
    const int r0 = blockIdx.x * TM;
    if (r0 >= nrows) return;
    const int ks = blockIdx.y;
    const int tid = threadIdx.x;          // 0..199
    const int tx = tid % 25;              // 4 cols each
    const int ty = tid / 25;              // 4 rows each
    const int kbase = ks * KCHUNK;

    if (tid < TM) {
        int pos = r0 + tid;
        int row = (pos < nrows) ? d_rows[pos] : -1;
        row_s[tid] = row;
        mz_s[tid] = (row >= 0) ? d_mz[row] : 0.f;
    }
    __syncthreads();

    // register prefetch state for one slab
    float  zr[4] = {0.f, 0.f, 0.f, 0.f};
    float2 Wv[5];
    int    pr_r[4], pr_kl[4];
#pragma unroll
    for (int j = 0; j < 4; j++) {
        int e = tid + j * 200;
        pr_r[j]  = e / KB;                // row-in-tile (e<640 valid)
        pr_kl[j] = e % KB;
    }

    auto prefetch = [&](int kglob) {      // kglob = absolute k of slab start
#pragma unroll
        for (int j = 0; j < 4; j++) {
            int e = tid + j * 200;
            if (e < KB * TM) {
                int row = row_s[pr_r[j]];
                zr[j] = (row >= 0) ? d_zbuf[(size_t)row * VOC + kglob + pr_kl[j]] : -1e30f;
            }
        }
        const float2* W2 = (const float2*)W;
#pragma unroll
        for (int j = 0; j < 5; j++) {
            int e = tid + j * 200;        // 0..999
            int kl = e / 50, c2 = e % 50;
            Wv[j] = W2[(size_t)(kglob + kl) * 50 + c2];
        }
    };

    prefetch(kbase);

    unsigned long long acc[8];            // 4 rows x 2 col-pairs
#pragma unroll
    for (int i = 0; i < 8; i++) acc[i] = 0ull;

    for (int it = 0; it < NITER; it++) {
        // math + STS from prefetched regs
#pragma unroll
        for (int j = 0; j < 4; j++) {
            int e = tid + j * 200;
            if (e < KB * TM) {
                float w = __expf(zr[j] - mz_s[pr_r[j]]);
                w2_s[pr_kl[j]][pr_r[j]] = make_float2(w, w);
            }
        }
#pragma unroll
        for (int j = 0; j < 5; j++) {
            int e = tid + j * 200;
            int kl = e / 50, c2 = e % 50;
            ((float2*)&W_s[kl][0])[c2] = Wv[j];
        }
        __syncthreads();

        // issue next slab's loads early (latency hidden under inner loop)
        if (it + 1 < NITER) prefetch(kbase + (it + 1) * KB);

        // inner MMA over the slab
#pragma unroll
        for (int k = 0; k < KB; k++) {
            ulonglong2 a01 = *(const ulonglong2*)&w2_s[k][ty * 4];
            ulonglong2 a23 = *(const ulonglong2*)&w2_s[k][ty * 4 + 2];
            union { float4 f; ulonglong2 u; } bb;
            bb.f = *(const float4*)&W_s[k][tx * 4];
            fma2(acc[0], a01.x, bb.u.x); fma2(acc[1], a01.x, bb.u.y);
            fma2(acc[2], a01.y, bb.u.x); fma2(acc[3], a01.y, bb.u.y);
            fma2(acc[4], a23.x, bb.u.x); fma2(acc[5], a23.x, bb.u.y);
            fma2(acc[6], a23.y, bb.u.x); fma2(acc[7], a23.y, bb.u.y);
        }
        __syncthreads();
    }

#pragma unroll
    for (int r = 0; r < 4; r++) {
        int pos = r0 + ty * 4 + r;
        float2 lo = unpk2(acc[r * 2]);
        float2 hi = unpk2(acc[r * 2 + 1]);
        float4 v = make_float4(lo.x, lo.y, hi.x, hi.y);
        *reinterpret_cast<float4*>(&d_part[((size_t)ks * RTOT + pos) * DIM + tx * 4]) = v;
    }
}

// ---------------- reduce split-K partials, normalize by s_z ----------------
__global__ __launch_bounds__(128) void reduce_kernel(float* __restrict__ out_emb)
{
    int pos = blockIdx.x;
    if (pos >= d_count) return;
    int d = threadIdx.x;
    if (d >= DIM) return;
    float s = 0.f;
#pragma unroll
    for (int k = 0; k < KSPLIT; k++)
        s += d_part[((size_t)k * RTOT + pos) * DIM + d];
    int row = d_rows[pos];
    out_emb[(size_t)row * DIM + d] = s / d_sz[row];
}

// ---------------- entropy loss ----------------
__global__ __launch_bounds__(256) void ent_kernel(const int* __restrict__ msk,
                                                  float* __restrict__ ent_out)
{
    __shared__ float ssum[256];
    __shared__ int   scnt[256];
    float s = 0.f; int c = 0;
    for (int i = threadIdx.x; i < RTOT; i += 256) { s += d_ent[i]; c += msk[i]; }
    ssum[threadIdx.x] = s; scnt[threadIdx.x] = c;
    __syncthreads();
    for (int off = 128; off; off >>= 1) {
        if (threadIdx.x < off) {
            ssum[threadIdx.x] += ssum[threadIdx.x + off];
            scnt[threadIdx.x] += scnt[threadIdx.x + off];
        }
        __syncthreads();
    }
    if (threadIdx.x == 0)
        ent_out[0] = ssum[0] / ((float)scnt[0] * (float)VOC);
}

// ---------------- launch ----------------
extern "C" void kernel_launch(void* const* d_in, const int* in_sizes, int n_in,
                              void* d_out, int out_size)
{
    const float* logits = (const float*)d_in[0];
    const float* gum    = (const float*)d_in[1];
    const void*  inp    = d_in[2];
    const int*   msk    = (const int*)d_in[3];
    const float* W      = (const float*)d_in[4];

    float* out      = (float*)d_out;
    float* out_word = out;                       // [2048]
    float* out_emb  = out + RTOT;                // [2048*100]
    float* out_ent  = out + RTOT + RTOT * DIM;   // [1]

    init_kernel<<<1, 1>>>(inp);
    stats_kernel<<<RTOT, 256>>>(logits, gum, inp, msk, out_word);
    fill_kernel<<<RTOT, 128>>>(W, out_emb);
    dim3 gg(RTOT / TM, KSPLIT);
    gemm_kernel<<<gg, 200>>>(W);
    reduce_kernel<<<RTOT, 128>>>(out_emb);
    ent_kernel<<<1, 256>>>(msk, out_ent);
}

// round 4
// speedup vs baseline: 1.5910x; 1.2604x over previous
#include <cuda_runtime.h>
#include <math.h>
#include <stdint.h>

#define RTOT 2048           // 8 * 256 rows
#define VOC  32000
#define DIM  100
#define DIMP 104            // padded to a multiple of 8
#define EPSC 1e-20f

#define TM     128              // rows per gemm tile
#define KSPLIT 32
#define KCHUNK (VOC / KSPLIT)   // 1000
#define KB     20               // k-depth staged per iteration
#define NITER  (KCHUNK / KB)    // 50
#define NTHR   208              // 16 row-groups x 13 col-groups
#define WSTR   132              // padded w_s row stride (floats, 16B-aligned rows)

// ---------------- scratch (__device__ globals; no allocation) ----------------
__device__ float d_mz[RTOT];
__device__ float d_sz[RTOT];
__device__ float d_ent[RTOT];
__device__ int   d_fillsrc[RTOT];   // -1 => gemm row, else gather source index
__device__ int   d_rows[RTOT];      // compacted gemm row list
__device__ int   d_count;
__device__ int   d_is64;
__device__ float d_part[(size_t)KSPLIT * RTOT * DIMP];     // 27.3 MB split-K partials
__device__ float d_zbuf[(size_t)RTOT * VOC];               // 262 MB: z for masked rows

// ---------------- f32x2 helpers (sm_103a packed fp32) ----------------
__device__ __forceinline__ void fma2(unsigned long long& d, unsigned long long a, unsigned long long b) {
    asm("fma.rn.f32x2 %0, %1, %2, %0;" : "+l"(d) : "l"(a), "l"(b));
}
__device__ __forceinline__ unsigned long long pk2(float lo, float hi) {
    unsigned long long r;
    asm("mov.b64 %0, {%1, %2};" : "=l"(r) : "f"(lo), "f"(hi));
    return r;
}
__device__ __forceinline__ float2 unpk2(unsigned long long v) {
    float2 r;
    asm("mov.b64 {%0, %1}, %2;" : "=f"(r.x), "=f"(r.y) : "l"(v));
    return r;
}

// Gumbel with argmax-safe inner log:
//  u <= 0.9 : t = -__logf(u)        (MUFU; rel err of t <= ~2e-6 there)
//  u >  0.9 : t = -log1p(-(1-u))    via 5-term Maclaurin (rel err ~2e-6)
__device__ __forceinline__ float gumbel_of(float u) {
    float t;
    if (u > 0.9f) {
        float d = 1.0f - u;   // exact (Sterbenz)
        t = d * (1.0f + d * (0.5f + d * (0.33333334f + d * (0.25f + d * 0.2f))));
    } else {
        t = -__logf(u + EPSC);
    }
    return -__logf(t + EPSC);
}

// ---------------- init ----------------
__global__ void init_kernel(const void* inp) {
    d_count = 0;
    const long long* p = (const long long*)inp;
    bool is64 = true;
#pragma unroll
    for (int i = 0; i < 8; i++) {
        long long v = p[i];
        if (v < 0 || v >= VOC) is64 = false;
    }
    d_is64 = is64 ? 1 : 0;
}

// ---------------- stats: one streaming pass per row; stores z for masked rows --
__global__ __launch_bounds__(256) void stats_kernel(
    const float* __restrict__ logits,
    const float* __restrict__ gum,
    const void*  __restrict__ inp,
    const int*   __restrict__ msk,
    float* __restrict__ out_word)
{
    const int row = blockIdx.x;
    const int m = msk[row];
    const float4* lrow = (const float4*)(logits + (size_t)row * VOC);
    const float4* grow = (const float4*)(gum    + (size_t)row * VOC);
    float4* zrow = (float4*)(d_zbuf + (size_t)row * VOC);

    float ml = -INFINITY, sl = 0.f, tl = 0.f;
    float mz = -INFINITY, sz = 0.f;
    int   ai = 0;

    for (int v4 = threadIdx.x; v4 < VOC / 4; v4 += 256) {
        float4 L = lrow[v4];
        float4 U = grow[v4];
        float ls[4] = {L.x, L.y, L.z, L.w};
        float us[4] = {U.x, U.y, U.z, U.w};
        float zs[4];
#pragma unroll
        for (int j = 0; j < 4; j++) {
            float l = ls[j];
            float z = l + gumbel_of(us[j]);
            zs[j] = z;
            if (l > ml) { float c = __expf(ml - l); sl = sl * c + 1.f; tl = tl * c + l; ml = l; }
            else        { float e = __expf(l - ml); sl += e; tl += l * e; }
            if (z > mz) { sz = sz * __expf(mz - z) + 1.f; mz = z; ai = 4 * v4 + j; }
            else        { sz += __expf(z - mz); }
        }
        if (m) zrow[v4] = make_float4(zs[0], zs[1], zs[2], zs[3]);
    }

    const unsigned FULL = 0xffffffffu;
#pragma unroll
    for (int off = 16; off; off >>= 1) {
        float ml2 = __shfl_down_sync(FULL, ml, off);
        float sl2 = __shfl_down_sync(FULL, sl, off);
        float tl2 = __shfl_down_sync(FULL, tl, off);
        float mz2 = __shfl_down_sync(FULL, mz, off);
        float sz2 = __shfl_down_sync(FULL, sz, off);
        int   ai2 = __shfl_down_sync(FULL, ai, off);
        if (ml2 > ml) { float c = __expf(ml - ml2); sl = sl * c + sl2; tl = tl * c + tl2; ml = ml2; }
        else if (sl2 > 0.f) { float c = __expf(ml2 - ml); sl += sl2 * c; tl += tl2 * c; }
        if (mz2 > mz || (mz2 == mz && ai2 < ai)) {
            float c = __expf(mz - mz2); sz = sz * c + sz2; mz = mz2; ai = ai2;
        } else if (sz2 > 0.f) { sz += sz2 * __expf(mz2 - mz); }
    }

    __shared__ float s_ml[8], s_sl[8], s_tl[8], s_mz[8], s_sz[8];
    __shared__ int   s_ai[8];
    int wid = threadIdx.x >> 5, lid = threadIdx.x & 31;
    if (lid == 0) { s_ml[wid]=ml; s_sl[wid]=sl; s_tl[wid]=tl; s_mz[wid]=mz; s_sz[wid]=sz; s_ai[wid]=ai; }
    __syncthreads();

    if (wid == 0) {
        bool live = (lid < 8);
        ml = live ? s_ml[lid] : -INFINITY;
        sl = live ? s_sl[lid] : 0.f;
        tl = live ? s_tl[lid] : 0.f;
        mz = live ? s_mz[lid] : -INFINITY;
        sz = live ? s_sz[lid] : 0.f;
        ai = live ? s_ai[lid] : 0x7fffffff;
#pragma unroll
        for (int off = 4; off; off >>= 1) {
            float ml2 = __shfl_down_sync(FULL, ml, off);
            float sl2 = __shfl_down_sync(FULL, sl, off);
            float tl2 = __shfl_down_sync(FULL, tl, off);
            float mz2 = __shfl_down_sync(FULL, mz, off);
            float sz2 = __shfl_down_sync(FULL, sz, off);
            int   ai2 = __shfl_down_sync(FULL, ai, off);
            if (ml2 > ml) { float c = __expf(ml - ml2); sl = sl * c + sl2; tl = tl * c + tl2; ml = ml2; }
            else if (sl2 > 0.f) { float c = __expf(ml2 - ml); sl += sl2 * c; tl += tl2 * c; }
            if (mz2 > mz || (mz2 == mz && ai2 < ai)) {
                float c = __expf(mz - mz2); sz = sz * c + sz2; mz = mz2; ai = ai2;
            } else if (sz2 > 0.f) { sz += sz2 * __expf(mz2 - mz); }
        }
        if (lid == 0) {
            float lse = ml + __logf(sl);
            float ent = tl / sl - lse;
            long long iw = d_is64 ? ((const long long*)inp)[row]
                                  : (long long)((const int*)inp)[row];
            bool safe = (ai != (int)iw);
            long long obf = m ? (safe ? (long long)ai : 0LL) : iw;
            out_word[row] = (float)obf;
            d_ent[row]    = m ? ent : 0.f;
            d_mz[row] = mz;
            d_sz[row] = sz;
            if (m && safe) {
                int p = atomicAdd(&d_count, 1);
                d_rows[p] = row;
                d_fillsrc[row] = -1;
            } else {
                d_fillsrc[row] = m ? 0 : (int)iw;
            }
        }
    }
}

// ---------------- fill: embedding gather for non-gemm rows ----------------
__global__ __launch_bounds__(128) void fill_kernel(const float* __restrict__ W,
                                                   float* __restrict__ out_emb)
{
    int row = blockIdx.x;
    int src = d_fillsrc[row];
    if (src < 0) return;
    int d = threadIdx.x;
    if (d < DIM)
        out_emb[(size_t)row * DIM + d] = W[(size_t)src * DIM + d];
}

// ---------------- gemm: 8x8 thread tile, reg-prefetch, packed f32x2 ----------
// block: 208 threads = 16 row-groups (8 rows) x 13 col-groups (8 cols, DIM pad 104)
__global__ __launch_bounds__(NTHR, 2) void gemm_kernel(const float* __restrict__ W)
{
    __shared__ float  w_s[KB][WSTR];        // [k][row]; padded stride (STS conflicts)
    __shared__ float2 W2_s[KB][52];         // [k][col/2]; 104 cols
    __shared__ float  mz_s[TM];
    __shared__ int    row_s[TM];

    const int nrows = d_count;
    const int r0 = blockIdx.x * TM;
    if (r0 >= nrows) return;
    const int ks = blockIdx.y;
    const int tid = threadIdx.x;            // 0..207
    const int tx = tid % 13;                // col group: 8 cols
    const int ty = tid / 13;                // row group: 8 rows
    const int kbase = ks * KCHUNK;

    if (tid < TM) {
        int pos = r0 + tid;
        int row = (pos < nrows) ? d_rows[pos] : -1;
        row_s[tid] = row;
        mz_s[tid] = (row >= 0) ? d_mz[row] : 0.f;
    }
    __syncthreads();

    // register prefetch state for one slab
    float  zr[13];
    float2 Wv[5];
#pragma unroll
    for (int j = 0; j < 13; j++) zr[j] = -1e30f;

    auto prefetch = [&](int kglob) {
        // z slab: KB*TM = 2560 elems; mapping e -> (r = e/KB, kl = e%KB)
#pragma unroll
        for (int j = 0; j < 13; j++) {
            int e = tid + j * NTHR;
            if (e < KB * TM) {
                int r  = e / KB;
                int kl = e % KB;
                int row = row_s[r];
                zr[j] = (row >= 0) ? d_zbuf[(size_t)row * VOC + kglob + kl] : -1e30f;
            }
        }
        // W slab: KB*50 real float2 (cols 0..99), pad c2=50,51 with zero
#pragma unroll
        for (int j = 0; j < 5; j++) {
            int e = tid + j * NTHR;        // 0..1039
            int kl = e / 52, c2 = e % 52;
            Wv[j] = (c2 < 50) ? ((const float2*)W)[(size_t)(kglob + kl) * 50 + c2]
                              : make_float2(0.f, 0.f);
        }
    };

    prefetch(kbase);

    unsigned long long acc[32];             // 8 rows x 4 f32x2 col-pairs
#pragma unroll
    for (int i = 0; i < 32; i++) acc[i] = 0ull;

    for (int it = 0; it < NITER; it++) {
        // commit prefetched slab to smem
#pragma unroll
        for (int j = 0; j < 13; j++) {
            int e = tid + j * NTHR;
            if (e < KB * TM) {
                int r  = e / KB;
                int kl = e % KB;
                w_s[kl][r] = __expf(zr[j] - mz_s[r]);
            }
        }
#pragma unroll
        for (int j = 0; j < 5; j++) {
            int e = tid + j * NTHR;
            int kl = e / 52, c2 = e % 52;
            W2_s[kl][c2] = Wv[j];
        }
        __syncthreads();

        // issue next slab's loads early (latency hidden under inner loop)
        if (it + 1 < NITER) prefetch(kbase + (it + 1) * KB);

        // inner MMA over the slab: per k, 4 LDS.128 -> 32 fma2
#pragma unroll
        for (int k = 0; k < KB; k++) {
            float4 a0 = *(const float4*)&w_s[k][ty * 8];
            float4 a1 = *(const float4*)&w_s[k][ty * 8 + 4];
            union { float4 f; ulonglong2 u; } b0, b1;
            b0.f = *(const float4*)&W2_s[k][tx * 4];
            b1.f = *(const float4*)&W2_s[k][tx * 4 + 2];
            unsigned long long A[8];
            A[0] = pk2(a0.x, a0.x); A[1] = pk2(a0.y, a0.y);
            A[2] = pk2(a0.z, a0.z); A[3] = pk2(a0.w, a0.w);
            A[4] = pk2(a1.x, a1.x); A[5] = pk2(a1.y, a1.y);
            A[6] = pk2(a1.z, a1.z); A[7] = pk2(a1.w, a1.w);
#pragma unroll
            for (int r = 0; r < 8; r++) {
                fma2(acc[r * 4 + 0], A[r], b0.u.x);
                fma2(acc[r * 4 + 1], A[r], b0.u.y);
                fma2(acc[r * 4 + 2], A[r], b1.u.x);
                fma2(acc[r * 4 + 3], A[r], b1.u.y);
            }
        }
        __syncthreads();
    }

    // write partials: 8 rows x 8 cols per thread
#pragma unroll
    for (int r = 0; r < 8; r++) {
        int pos = r0 + ty * 8 + r;
        float2 p0 = unpk2(acc[r * 4 + 0]);
        float2 p1 = unpk2(acc[r * 4 + 1]);
        float2 p2 = unpk2(acc[r * 4 + 2]);
        float2 p3 = unpk2(acc[r * 4 + 3]);
        float* dst = &d_part[((size_t)ks * RTOT + pos) * DIMP + tx * 8];
        *(float4*)(dst)     = make_float4(p0.x, p0.y, p1.x, p1.y);
        *(float4*)(dst + 4) = make_float4(p2.x, p2.y, p3.x, p3.y);
    }
}

// ---------------- reduce split-K partials, normalize by s_z ----------------
__global__ __launch_bounds__(128) void reduce_kernel(float* __restrict__ out_emb)
{
    int pos = blockIdx.x;
    if (pos >= d_count) return;
    int d = threadIdx.x;
    if (d >= DIM) return;
    float s = 0.f;
#pragma unroll
    for (int k = 0; k < KSPLIT; k++)
        s += d_part[((size_t)k * RTOT + pos) * DIMP + d];
    int row = d_rows[pos];
    out_emb[(size_t)row * DIM + d] = s / d_sz[row];
}

// ---------------- entropy loss ----------------
__global__ __launch_bounds__(256) void ent_kernel(const int* __restrict__ msk,
                                                  float* __restrict__ ent_out)
{
    __shared__ float ssum[256];
    __shared__ int   scnt[256];
    float s = 0.f; int c = 0;
    for (int i = threadIdx.x; i < RTOT; i += 256) { s += d_ent[i]; c += msk[i]; }
    ssum[threadIdx.x] = s; scnt[threadIdx.x] = c;
    __syncthreads();
    for (int off = 128; off; off >>= 1) {
        if (threadIdx.x < off) {
            ssum[threadIdx.x] += ssum[threadIdx.x + off];
            scnt[threadIdx.x] += scnt[threadIdx.x + off];
        }
        __syncthreads();
    }
    if (threadIdx.x == 0)
        ent_out[0] = ssum[0] / ((float)scnt[0] * (float)VOC);
}

// ---------------- launch ----------------
extern "C" void kernel_launch(void* const* d_in, const int* in_sizes, int n_in,
                              void* d_out, int out_size)
{
    const float* logits = (const float*)d_in[0];
    const float* gum    = (const float*)d_in[1];
    const void*  inp    = d_in[2];
    const int*   msk    = (const int*)d_in[3];
    const float* W      = (const float*)d_in[4];

    float* out      = (float*)d_out;
    float* out_word = out;                       // [2048]
    float* out_emb  = out + RTOT;                // [2048*100]
    float* out_ent  = out + RTOT + RTOT * DIM;   // [1]

    init_kernel<<<1, 1>>>(inp);
    stats_kernel<<<RTOT, 256>>>(logits, gum, inp, msk, out_word);
    fill_kernel<<<RTOT, 128>>>(W, out_emb);
    dim3 gg(RTOT / TM, KSPLIT);
    gemm_kernel<<<gg, NTHR>>>(W);
    reduce_kernel<<<RTOT, 128>>>(out_emb);
    ent_kernel<<<1, 256>>>(msk, out_ent);
}